// round 8
// baseline (speedup 1.0000x reference)
#include <cuda_runtime.h>
#include <math.h>
#include <cstdint>

#define Bn 4
#define Tn 8
#define Hn 256
#define Wn 256
#define NPIX (Bn*Tn*Hn*Wn)   // 2,097,152 elements per field

typedef unsigned long long u64;

// Scratch (static device globals -- no allocation allowed)
// fields: 0:kappa^2 1:m1 2:m2 3:Hxx 4:(Hxy+Hyx) 5:unused 6:Hyy 7:D
__device__ float g_fields[8][NPIX];
__device__ float g_v[NPIX];                     // v = A(x)
__device__ __align__(16) float g_ws[72 * 64];   // transposed weights [k][o]
__constant__ __align__(16) float c_ws[72 * 64]; // same, in constant bank
__device__ double g_acc[2];                     // [0]=sum(D r^2) [1]=sum(log D)

__global__ void init_acc_kernel() {
    g_acc[0] = 0.0;
    g_acc[1] = 0.0;
}

__global__ void dummy_kernel() {}

// One-off: transpose cw[o][k] (o-major, 64x72) -> g_ws[k][o] (k-major, 72x64).
__global__ __launch_bounds__(256) void transpose_w_kernel(const float* __restrict__ cw)
{
    int i = blockIdx.x * 256 + threadIdx.x;
    if (i < 72 * 64) {
        int o = i / 72, k = i % 72;
        g_ws[k * 64 + o] = cw[i];
    }
}

// ---------------------------------------------------------------------------
// packed f32x2 helpers (Blackwell)
// ---------------------------------------------------------------------------
__device__ __forceinline__ u64 fma2(u64 a, u64 b, u64 c) {
    u64 d;
    asm("fma.rn.f32x2 %0, %1, %2, %3;" : "=l"(d) : "l"(a), "l"(b), "l"(c));
    return d;
}
__device__ __forceinline__ u64 dup2(float x) {
    u64 d;
    unsigned int xi = __float_as_uint(x);
    asm("mov.b64 %0, {%1, %1};" : "=l"(d) : "r"(xi));
    return d;
}
__device__ __forceinline__ void unpack2(u64 v, float& lo, float& hi) {
    unsigned int a, b;
    asm("mov.b64 {%0, %1}, %2;" : "=r"(a), "=r"(b) : "l"(v));
    lo = __uint_as_float(a);
    hi = __uint_as_float(b);
}

// ---------------------------------------------------------------------------
// Kernel 1: 3x3 conv (8 -> 64 channels), f32x2 packed FMA, ky-window reuse,
// weights from __constant__ (warp-uniform -> uniform-const path, no smem).
// Tile: 32 wide x 4 tall. 256 threads, warp id = output group g (8 channels).
// Each thread: 4 rows x 4 channel-pairs = 16 u64 accumulators.
// ---------------------------------------------------------------------------
#define TW 32
#define TH 4

__global__ __launch_bounds__(256, 4) void conv_kernel(const float* __restrict__ x)
{
    __shared__ float xs[8][TH + 2][TW + 2];        // 8 ch x 6 x 34  (6.5KB)
    __shared__ float hy[TH][8][32];                // warp5's 0.1*tanh (4KB)

    const int tid = threadIdx.x;
    const int b  = blockIdx.z;
    const int h0 = blockIdx.y * TH;
    const int w0 = blockIdx.x * TW;

    // x tile with halo 1 (zero Dirichlet)
    for (int i = tid; i < 8 * (TH + 2) * (TW + 2); i += 256) {
        int ci  = i / ((TH + 2) * (TW + 2));
        int rem = i % ((TH + 2) * (TW + 2));
        int yy  = rem / (TW + 2);
        int xx  = rem % (TW + 2);
        int gy = h0 - 1 + yy, gx = w0 - 1 + xx;
        float v = 0.f;
        if (gy >= 0 && gy < Hn && gx >= 0 && gx < Wn)
            v = x[(((b * Tn) + ci) * Hn + gy) * Wn + gx];
        xs[ci][yy][xx] = v;
    }
    __syncthreads();

    const int tn = tid >> 5;   // warp = group g (0..7)
    const int tm = tid & 31;   // pixel column within tile

    u64 acc2[TH][4];
    #pragma unroll
    for (int i = 0; i < TH; i++)
        #pragma unroll
        for (int j = 0; j < 4; j++) acc2[i][j] = 0ull;

    const int obase = tn * 8;
    for (int ci = 0; ci < 8; ci++) {
        #pragma unroll
        for (int kx = 0; kx < 3; kx++) {
            // 6-row column window at tm+kx, loaded once, reused over ky
            u64 xd[TH + 2];
            #pragma unroll
            for (int r = 0; r < TH + 2; r++)
                xd[r] = dup2(xs[ci][r][tm + kx]);
            #pragma unroll
            for (int ky = 0; ky < 3; ky++) {
                const int k = ci * 9 + ky * 3 + kx;
                // warp-uniform constant loads (uniform-const port)
                const ulonglong2* wp = (const ulonglong2*)&c_ws[k * 64 + obase];
                ulonglong2 wa = wp[0];   // pairs (0,1) (2,3)
                ulonglong2 wb = wp[1];   // pairs (4,5) (6,7)
                #pragma unroll
                for (int i = 0; i < TH; i++) {
                    u64 xv = xd[i + ky];
                    acc2[i][0] = fma2(xv, wa.x, acc2[i][0]);
                    acc2[i][1] = fma2(xv, wa.y, acc2[i][1]);
                    acc2[i][2] = fma2(xv, wb.x, acc2[i][2]);
                    acc2[i][3] = fma2(xv, wb.y, acc2[i][3]);
                }
            }
        }
    }

    // warp 5 (Hyx): deposit 0.1*tanh into smem for warp 4 to merge
    if (tn == 5) {
        #pragma unroll
        for (int i = 0; i < TH; i++) {
            #pragma unroll
            for (int j2 = 0; j2 < 4; j2++) {
                float t0, t1;
                unpack2(acc2[i][j2], t0, t1);
                hy[i][2 * j2][tm]     = 0.1f * tanhf(t0);
                hy[i][2 * j2 + 1][tm] = 0.1f * tanhf(t1);
            }
        }
    }
    __syncthreads();

    float lsum = 0.f;
    if (tn != 5) {
        #pragma unroll
        for (int i = 0; i < TH; i++) {
            const int h = h0 + i;
            #pragma unroll
            for (int j2 = 0; j2 < 4; j2++) {
                float t0, t1;
                unpack2(acc2[i][j2], t0, t1);
                float r0, r1;
                if (tn == 0) {                       // kappa -> kappa^2
                    float s0 = 1.f / (1.f + expf(-t0));
                    float s1 = 1.f / (1.f + expf(-t1));
                    float k0 = s0 * 0.99f + 0.01f;
                    float k1 = s1 * 0.99f + 0.01f;
                    r0 = k0 * k0; r1 = k1 * k1;
                } else if (tn == 1 || tn == 2) {     // m1, m2 raw
                    r0 = t0; r1 = t1;
                } else if (tn == 3 || tn == 6) {     // Hxx, Hyy
                    r0 = (1.f / (1.f + expf(-t0))) * 0.99f + 0.01f;
                    r1 = (1.f / (1.f + expf(-t1))) * 0.99f + 0.01f;
                } else if (tn == 4) {                // Hxy + Hyx (merged)
                    r0 = 0.1f * tanhf(t0) + hy[i][2 * j2][tm];
                    r1 = 0.1f * tanhf(t1) + hy[i][2 * j2 + 1][tm];
                } else {                             // tau -> D = 1/tau^2
                    float s0 = 1.f / (1.f + expf(-t0));
                    float s1 = 1.f / (1.f + expf(-t1));
                    float ta0 = s0 * 9.9f + 0.1f;
                    float ta1 = s1 * 9.9f + 0.1f;
                    r0 = 1.f / (ta0 * ta0);
                    r1 = 1.f / (ta1 * ta1);
                    lsum += logf(r0) + logf(r1);
                }
                const int j0 = 2 * j2;
                g_fields[tn][(((b * Tn) + j0)     * Hn + h) * Wn + w0 + tm] = r0;
                g_fields[tn][(((b * Tn) + j0 + 1) * Hn + h) * Wn + w0 + tm] = r1;
            }
        }
    }

    if (tn == 7) {   // accumulate logdet(D)
        #pragma unroll
        for (int off = 16; off; off >>= 1)
            lsum += __shfl_down_sync(0xffffffffu, lsum, off);
        if (tm == 0) atomicAdd(&g_acc[1], (double)lsum);
    }
}

// ---------------------------------------------------------------------------
// Vectorized stencil: operator A on 4 consecutive pixels.
// ---------------------------------------------------------------------------
__device__ __forceinline__ void loadrow6(const float* __restrict__ row, int w4,
                                         float* arr)
{
    float4 v = *(const float4*)(row + w4);
    arr[0] = (w4 > 0)      ? row[w4 - 1] : 0.f;
    arr[1] = v.x; arr[2] = v.y; arr[3] = v.z; arr[4] = v.w;
    arr[5] = (w4 + 4 < Wn) ? row[w4 + 4] : 0.f;
}

__device__ __forceinline__ float4 applyA4(const float* __restrict__ u,
                                          int base, int h, int w4)
{
    float cc[6], uu[6], dd[6];
    const float* row = u + base + h * Wn;
    loadrow6(row, w4, cc);
    if (h > 0)       loadrow6(row - Wn, w4, uu);
    else { uu[0]=uu[1]=uu[2]=uu[3]=uu[4]=uu[5]=0.f; }
    if (h + 1 < Hn)  loadrow6(row + Wn, w4, dd);
    else { dd[0]=dd[1]=dd[2]=dd[3]=dd[4]=dd[5]=0.f; }

    const int p = base + h * Wn + w4;
    float4 q0 = *(const float4*)&g_fields[0][p];
    float4 q1 = *(const float4*)&g_fields[1][p];
    float4 q2 = *(const float4*)&g_fields[2][p];
    float4 q3 = *(const float4*)&g_fields[3][p];
    float4 q4 = *(const float4*)&g_fields[4][p];
    float4 q6 = *(const float4*)&g_fields[6][p];
    float f0a[4] = {q0.x, q0.y, q0.z, q0.w};
    float f1a[4] = {q1.x, q1.y, q1.z, q1.w};
    float f2a[4] = {q2.x, q2.y, q2.z, q2.w};
    float f3a[4] = {q3.x, q3.y, q3.z, q3.w};
    float f4a[4] = {q4.x, q4.y, q4.z, q4.w};
    float f6a[4] = {q6.x, q6.y, q6.z, q6.w};

    float out[4];
    #pragma unroll
    for (int j = 0; j < 4; j++) {
        float c   = cc[j + 1];
        float dx  = 0.5f  * (cc[j + 2] - cc[j]);
        float dy  = 0.5f  * (dd[j + 1] - uu[j + 1]);
        float dxx = cc[j + 2] + cc[j] - 2.f * c;
        float dyy = dd[j + 1] + uu[j + 1] - 2.f * c;
        float dxy = 0.25f * ((dd[j + 2] - uu[j + 2]) - (dd[j] - uu[j]));
        out[j] = f0a[j] * c + f1a[j] * dx + f2a[j] * dy
               - (f3a[j] * dxx + f6a[j] * dyy + f4a[j] * dxy);
    }
    return make_float4(out[0], out[1], out[2], out[3]);
}

// Kernel 2: v = A(x)   -- 256 threads, 4 rows x 64 float4-lanes per block
__global__ __launch_bounds__(256) void stencil1_kernel(const float* __restrict__ x)
{
    const int tx = threadIdx.x & 63;
    const int ty = threadIdx.x >> 6;
    const int h  = blockIdx.x * 4 + ty;
    const int t  = blockIdx.y;
    const int b  = blockIdx.z;
    const int base = ((b * Tn + t) * Hn) * Wn;
    const int w4 = tx * 4;
    float4 r = applyA4(x, base, h, w4);
    *(float4*)&g_v[base + h * Wn + w4] = r;
}

// Kernel 3: r = x + A(v) - x_prev ; accumulate sum(D r^2)
__global__ __launch_bounds__(256) void stencil2_kernel(const float* __restrict__ x)
{
    const int tx = threadIdx.x & 63;
    const int ty = threadIdx.x >> 6;
    const int h  = blockIdx.x * 4 + ty;
    const int t  = blockIdx.y;
    const int b  = blockIdx.z;
    const int base = ((b * Tn + t) * Hn) * Wn;
    const int w4 = tx * 4;
    const int p  = base + h * Wn + w4;

    float4 Av = applyA4(g_v, base, h, w4);
    float4 xv = *(const float4*)&x[p];
    float4 xp = make_float4(0.f, 0.f, 0.f, 0.f);
    if (t > 0) xp = *(const float4*)&x[p - Hn * Wn];
    float4 f7 = *(const float4*)&g_fields[7][p];

    float r0 = xv.x + Av.x - xp.x;
    float r1 = xv.y + Av.y - xp.y;
    float r2 = xv.z + Av.z - xp.z;
    float r3 = xv.w + Av.w - xp.w;
    float val = f7.x * r0 * r0 + f7.y * r1 * r1 + f7.z * r2 * r2 + f7.w * r3 * r3;

    #pragma unroll
    for (int off = 16; off; off >>= 1)
        val += __shfl_down_sync(0xffffffffu, val, off);

    __shared__ float red[8];
    const int lane = threadIdx.x & 31;
    const int wid  = threadIdx.x >> 5;
    if (lane == 0) red[wid] = val;
    __syncthreads();
    if (wid == 0) {
        float s = (lane < 8) ? red[lane] : 0.f;
        #pragma unroll
        for (int off = 4; off; off >>= 1)
            s += __shfl_down_sync(0xffffffffu, s, off);
        if (lane == 0) atomicAdd(&g_acc[0], (double)s);
    }
}

__global__ void finalize_kernel(float* __restrict__ out)
{
    out[0] = (float)(0.5 * (g_acc[0] - g_acc[1]));
}

// ---------------------------------------------------------------------------
extern "C" void kernel_launch(void* const* d_in, const int* in_sizes, int n_in,
                              void* d_out, int out_size)
{
    const float* x  = (const float*)d_in[0];
    const float* cw = (const float*)d_in[1];
    float* out = (float*)d_out;

    init_acc_kernel<<<1, 1>>>();          // kernel 1
    transpose_w_kernel<<<18, 256>>>(cw);  // kernel 2

    // device-to-device async copy into constant bank (graph-capturable)
    void* ws_ptr = nullptr;
    cudaGetSymbolAddress(&ws_ptr, g_ws);
    cudaMemcpyToSymbolAsync(c_ws, ws_ptr, 72 * 64 * sizeof(float), 0,
                            cudaMemcpyDeviceToDevice, 0);

    dummy_kernel<<<1, 1>>>();             // kernel 3 (ncu captures 4th kernel)

    dim3 gA(Wn / TW, Hn / TH, Bn);        // 8 x 64 x 4 = 2048 blocks
    conv_kernel<<<gA, 256>>>(x);          // kernel 4 -> ncu target

    dim3 gS(Hn / 4, Tn, Bn);              // 64 x 8 x 4 = 2048 blocks, 256 thr
    stencil1_kernel<<<gS, 256>>>(x);
    stencil2_kernel<<<gS, 256>>>(x);

    finalize_kernel<<<1, 1>>>(out);
}

// round 9
// speedup vs baseline: 1.3989x; 1.3989x over previous
#include <cuda_runtime.h>
#include <math.h>
#include <cstdint>

#define Bn 4
#define Tn 8
#define Hn 256
#define Wn 256
#define NPIX (Bn*Tn*Hn*Wn)   // 2,097,152 elements per field

// Scratch (static device globals -- no allocation allowed)
// fields: 0:kappa^2 1:m1 2:m2 3:Hxx 4:(Hxy+Hyx) 5:unused 6:Hyy 7:D
__device__ float g_fields[8][NPIX];
__device__ float g_v[NPIX];                     // v = A(x)
__device__ __align__(16) float g_ws[72 * 64];   // transposed weights [k][o]
__device__ double g_acc[2];                     // [0]=sum(D r^2) [1]=sum(log D)

__global__ void init_acc_kernel() {
    g_acc[0] = 0.0;
    g_acc[1] = 0.0;
}

__global__ void dummy_kernel() {}

// One-off: transpose cw[o][k] (o-major, 64x72) -> g_ws[k][o] (k-major, 72x64).
__global__ __launch_bounds__(256) void transpose_w_kernel(const float* __restrict__ cw)
{
    int i = blockIdx.x * 256 + threadIdx.x;
    if (i < 72 * 64) {
        int o = i / 72, k = i % 72;
        g_ws[k * 64 + o] = cw[i];
    }
}

// ---------------------------------------------------------------------------
// Kernel 1: 3x3 conv (8 -> 64 channels), scalar FFMA, ky-reuse window,
// smem weights (coalesced copy of pre-transposed g_ws), 4 blocks/SM.
// Tile: 32 wide x 4 tall. 256 threads, warp id = output group g (8 channels).
// Each thread: 4 rows x 8 channels = 32 fp32 accumulators.
// ---------------------------------------------------------------------------
#define TW 32
#define TH 4

__global__ __launch_bounds__(256, 4) void conv_kernel(const float* __restrict__ x)
{
    __shared__ float xs[8][TH + 2][TW + 2];        // 8 ch x 6 x 34  (6.5KB)
    __shared__ __align__(16) float ws[72 * 64];    // [k][o], o fastest (18KB)
    __shared__ float hy[TH][8][32];                // warp5's 0.1*tanh (4KB)

    const int tid = threadIdx.x;
    const int b  = blockIdx.z;
    const int h0 = blockIdx.y * TH;
    const int w0 = blockIdx.x * TW;

    // coalesced copy of pre-transposed weights (float4)
    {
        const float4* src = (const float4*)g_ws;
        float4* dst = (float4*)ws;
        #pragma unroll
        for (int i = tid; i < 72 * 16; i += 256)
            dst[i] = src[i];
    }
    // x tile with halo 1 (zero Dirichlet)
    for (int i = tid; i < 8 * (TH + 2) * (TW + 2); i += 256) {
        int ci  = i / ((TH + 2) * (TW + 2));
        int rem = i % ((TH + 2) * (TW + 2));
        int yy  = rem / (TW + 2);
        int xx  = rem % (TW + 2);
        int gy = h0 - 1 + yy, gx = w0 - 1 + xx;
        float v = 0.f;
        if (gy >= 0 && gy < Hn && gx >= 0 && gx < Wn)
            v = x[(((b * Tn) + ci) * Hn + gy) * Wn + gx];
        xs[ci][yy][xx] = v;
    }
    __syncthreads();

    const int tn = tid >> 5;   // warp = group g (0..7)
    const int tm = tid & 31;   // pixel column within tile

    float acc[TH][8];
    #pragma unroll
    for (int i = 0; i < TH; i++)
        #pragma unroll
        for (int j = 0; j < 8; j++) acc[i][j] = 0.f;

    const int obase = tn * 8;
    for (int ci = 0; ci < 8; ci++) {
        #pragma unroll
        for (int kx = 0; kx < 3; kx++) {
            // 6-row column window at tm+kx, loaded once, reused over ky
            float xd[TH + 2];
            #pragma unroll
            for (int r = 0; r < TH + 2; r++)
                xd[r] = xs[ci][r][tm + kx];
            #pragma unroll
            for (int ky = 0; ky < 3; ky++) {
                const int k = ci * 9 + ky * 3 + kx;
                float4 wv0 = *(const float4*)&ws[k * 64 + obase];
                float4 wv1 = *(const float4*)&ws[k * 64 + obase + 4];
                #pragma unroll
                for (int i = 0; i < TH; i++) {
                    float xv = xd[i + ky];
                    acc[i][0] += xv * wv0.x;
                    acc[i][1] += xv * wv0.y;
                    acc[i][2] += xv * wv0.z;
                    acc[i][3] += xv * wv0.w;
                    acc[i][4] += xv * wv1.x;
                    acc[i][5] += xv * wv1.y;
                    acc[i][6] += xv * wv1.z;
                    acc[i][7] += xv * wv1.w;
                }
            }
        }
    }

    // warp 5 (Hyx): deposit 0.1*tanh into smem for warp 4 to merge
    if (tn == 5) {
        #pragma unroll
        for (int i = 0; i < TH; i++)
            #pragma unroll
            for (int j = 0; j < 8; j++)
                hy[i][j][tm] = 0.1f * tanhf(acc[i][j]);
    }
    __syncthreads();

    float lsum = 0.f;
    if (tn != 5) {
        #pragma unroll
        for (int i = 0; i < TH; i++) {
            const int h = h0 + i;
            #pragma unroll
            for (int j = 0; j < 8; j++) {
                float a = acc[i][j];
                float r;
                if (tn == 0) {                       // kappa -> kappa^2
                    float s = 1.f / (1.f + expf(-a));
                    float kp = s * 0.99f + 0.01f;
                    r = kp * kp;
                } else if (tn == 1 || tn == 2) {     // m1, m2 raw
                    r = a;
                } else if (tn == 3 || tn == 6) {     // Hxx, Hyy
                    r = (1.f / (1.f + expf(-a))) * 0.99f + 0.01f;
                } else if (tn == 4) {                // Hxy + Hyx (merged)
                    r = 0.1f * tanhf(a) + hy[i][j][tm];
                } else {                             // tau -> D = 1/tau^2
                    float s = 1.f / (1.f + expf(-a));
                    float tau = s * 9.9f + 0.1f;
                    r = 1.f / (tau * tau);
                    lsum += logf(r);
                }
                g_fields[tn][(((b * Tn) + j) * Hn + h) * Wn + w0 + tm] = r;
            }
        }
    }

    if (tn == 7) {   // accumulate logdet(D)
        #pragma unroll
        for (int off = 16; off; off >>= 1)
            lsum += __shfl_down_sync(0xffffffffu, lsum, off);
        if (tm == 0) atomicAdd(&g_acc[1], (double)lsum);
    }
}

// ---------------------------------------------------------------------------
// Vectorized stencil: operator A on 4 consecutive pixels.
// ---------------------------------------------------------------------------
__device__ __forceinline__ void loadrow6(const float* __restrict__ row, int w4,
                                         float* arr)
{
    float4 v = *(const float4*)(row + w4);
    arr[0] = (w4 > 0)      ? row[w4 - 1] : 0.f;
    arr[1] = v.x; arr[2] = v.y; arr[3] = v.z; arr[4] = v.w;
    arr[5] = (w4 + 4 < Wn) ? row[w4 + 4] : 0.f;
}

__device__ __forceinline__ float4 applyA4(const float* __restrict__ u,
                                          int base, int h, int w4)
{
    float cc[6], uu[6], dd[6];
    const float* row = u + base + h * Wn;
    loadrow6(row, w4, cc);
    if (h > 0)       loadrow6(row - Wn, w4, uu);
    else { uu[0]=uu[1]=uu[2]=uu[3]=uu[4]=uu[5]=0.f; }
    if (h + 1 < Hn)  loadrow6(row + Wn, w4, dd);
    else { dd[0]=dd[1]=dd[2]=dd[3]=dd[4]=dd[5]=0.f; }

    const int p = base + h * Wn + w4;
    float4 q0 = *(const float4*)&g_fields[0][p];
    float4 q1 = *(const float4*)&g_fields[1][p];
    float4 q2 = *(const float4*)&g_fields[2][p];
    float4 q3 = *(const float4*)&g_fields[3][p];
    float4 q4 = *(const float4*)&g_fields[4][p];
    float4 q6 = *(const float4*)&g_fields[6][p];
    float f0a[4] = {q0.x, q0.y, q0.z, q0.w};
    float f1a[4] = {q1.x, q1.y, q1.z, q1.w};
    float f2a[4] = {q2.x, q2.y, q2.z, q2.w};
    float f3a[4] = {q3.x, q3.y, q3.z, q3.w};
    float f4a[4] = {q4.x, q4.y, q4.z, q4.w};
    float f6a[4] = {q6.x, q6.y, q6.z, q6.w};

    float out[4];
    #pragma unroll
    for (int j = 0; j < 4; j++) {
        float c   = cc[j + 1];
        float dx  = 0.5f  * (cc[j + 2] - cc[j]);
        float dy  = 0.5f  * (dd[j + 1] - uu[j + 1]);
        float dxx = cc[j + 2] + cc[j] - 2.f * c;
        float dyy = dd[j + 1] + uu[j + 1] - 2.f * c;
        float dxy = 0.25f * ((dd[j + 2] - uu[j + 2]) - (dd[j] - uu[j]));
        out[j] = f0a[j] * c + f1a[j] * dx + f2a[j] * dy
               - (f3a[j] * dxx + f6a[j] * dyy + f4a[j] * dxy);
    }
    return make_float4(out[0], out[1], out[2], out[3]);
}

// Kernel 2: v = A(x)   -- 256 threads, 4 rows x 64 float4-lanes per block
__global__ __launch_bounds__(256) void stencil1_kernel(const float* __restrict__ x)
{
    const int tx = threadIdx.x & 63;
    const int ty = threadIdx.x >> 6;
    const int h  = blockIdx.x * 4 + ty;
    const int t  = blockIdx.y;
    const int b  = blockIdx.z;
    const int base = ((b * Tn + t) * Hn) * Wn;
    const int w4 = tx * 4;
    float4 r = applyA4(x, base, h, w4);
    *(float4*)&g_v[base + h * Wn + w4] = r;
}

// Kernel 3: r = x + A(v) - x_prev ; accumulate sum(D r^2)
__global__ __launch_bounds__(256) void stencil2_kernel(const float* __restrict__ x)
{
    const int tx = threadIdx.x & 63;
    const int ty = threadIdx.x >> 6;
    const int h  = blockIdx.x * 4 + ty;
    const int t  = blockIdx.y;
    const int b  = blockIdx.z;
    const int base = ((b * Tn + t) * Hn) * Wn;
    const int w4 = tx * 4;
    const int p  = base + h * Wn + w4;

    float4 Av = applyA4(g_v, base, h, w4);
    float4 xv = *(const float4*)&x[p];
    float4 xp = make_float4(0.f, 0.f, 0.f, 0.f);
    if (t > 0) xp = *(const float4*)&x[p - Hn * Wn];
    float4 f7 = *(const float4*)&g_fields[7][p];

    float r0 = xv.x + Av.x - xp.x;
    float r1 = xv.y + Av.y - xp.y;
    float r2 = xv.z + Av.z - xp.z;
    float r3 = xv.w + Av.w - xp.w;
    float val = f7.x * r0 * r0 + f7.y * r1 * r1 + f7.z * r2 * r2 + f7.w * r3 * r3;

    #pragma unroll
    for (int off = 16; off; off >>= 1)
        val += __shfl_down_sync(0xffffffffu, val, off);

    __shared__ float red[8];
    const int lane = threadIdx.x & 31;
    const int wid  = threadIdx.x >> 5;
    if (lane == 0) red[wid] = val;
    __syncthreads();
    if (wid == 0) {
        float s = (lane < 8) ? red[lane] : 0.f;
        #pragma unroll
        for (int off = 4; off; off >>= 1)
            s += __shfl_down_sync(0xffffffffu, s, off);
        if (lane == 0) atomicAdd(&g_acc[0], (double)s);
    }
}

__global__ void finalize_kernel(float* __restrict__ out)
{
    out[0] = (float)(0.5 * (g_acc[0] - g_acc[1]));
}

// ---------------------------------------------------------------------------
extern "C" void kernel_launch(void* const* d_in, const int* in_sizes, int n_in,
                              void* d_out, int out_size)
{
    const float* x  = (const float*)d_in[0];
    const float* cw = (const float*)d_in[1];
    float* out = (float*)d_out;

    init_acc_kernel<<<1, 1>>>();          // kernel 1
    transpose_w_kernel<<<18, 256>>>(cw);  // kernel 2
    dummy_kernel<<<1, 1>>>();             // kernel 3 (ncu captures kernel 4)

    dim3 gA(Wn / TW, Hn / TH, Bn);        // 8 x 64 x 4 = 2048 blocks
    conv_kernel<<<gA, 256>>>(x);          // kernel 4 -> ncu target

    dim3 gS(Hn / 4, Tn, Bn);              // 64 x 8 x 4 = 2048 blocks, 256 thr
    stencil1_kernel<<<gS, 256>>>(x);
    stencil2_kernel<<<gS, 256>>>(x);

    finalize_kernel<<<1, 1>>>(out);
}

// round 10
// speedup vs baseline: 1.6890x; 1.2074x over previous
#include <cuda_runtime.h>
#include <math.h>
#include <cstdint>

#define Bn 4
#define Tn 8
#define Hn 256
#define Wn 256
#define NPIX (Bn*Tn*Hn*Wn)   // 2,097,152 elements per field

typedef unsigned long long u64;

// Scratch (static device globals -- no allocation allowed)
// fields: 0:kappa^2 1:m1 2:m2 3:Hxx 4:(Hxy+Hyx) 5:unused 6:Hyy 7:D
__device__ float g_fields[8][NPIX];
__device__ float g_v[NPIX];                     // v = A(x)
__device__ __align__(16) float g_ws[72 * 64];   // transposed weights [k][o]
__device__ double g_acc[2];                     // [0]=sum(D r^2) [1]=sum(log D)

__global__ void init_acc_kernel() {
    g_acc[0] = 0.0;
    g_acc[1] = 0.0;
}

__global__ void dummy_kernel() {}

// One-off: transpose cw[o][k] (o-major, 64x72) -> g_ws[k][o] (k-major, 72x64).
__global__ __launch_bounds__(256) void transpose_w_kernel(const float* __restrict__ cw)
{
    int i = blockIdx.x * 256 + threadIdx.x;
    if (i < 72 * 64) {
        int o = i / 72, k = i % 72;
        g_ws[k * 64 + o] = cw[i];
    }
}

// ---------------------------------------------------------------------------
// packed f32x2 helpers (Blackwell)
// ---------------------------------------------------------------------------
__device__ __forceinline__ u64 fma2(u64 a, u64 b, u64 c) {
    u64 d;
    asm("fma.rn.f32x2 %0, %1, %2, %3;" : "=l"(d) : "l"(a), "l"(b), "l"(c));
    return d;
}
__device__ __forceinline__ u64 dup2(float x) {
    u64 d;
    unsigned int xi = __float_as_uint(x);
    asm("mov.b64 %0, {%1, %1};" : "=l"(d) : "r"(xi));
    return d;
}
__device__ __forceinline__ void unpack2(u64 v, float& lo, float& hi) {
    unsigned int a, b;
    asm("mov.b64 {%0, %1}, %2;" : "=r"(a), "=r"(b) : "l"(v));
    lo = __uint_as_float(a);
    hi = __uint_as_float(b);
}

// ---------------------------------------------------------------------------
// Kernel 1: 3x3 conv (8 -> 64 channels), f32x2 packed FMA, ky-reuse window,
// smem weights, 4 blocks/SM, ci-loop unroll 2 for cross-iteration ILP.
// Tile: 32 wide x 4 tall. 256 threads, warp id = output group g (8 channels).
// Each thread: 4 rows x 4 channel-pairs = 16 u64 accumulators.
// ---------------------------------------------------------------------------
#define TW 32
#define TH 4

__global__ __launch_bounds__(256, 4) void conv_kernel(const float* __restrict__ x)
{
    __shared__ float xs[8][TH + 2][TW + 2];        // 8 ch x 6 x 34  (6.5KB)
    __shared__ __align__(16) float ws[72 * 64];    // [k][o], o fastest (18KB)
    __shared__ float hy[TH][8][32];                // warp5's 0.1*tanh (4KB)

    const int tid = threadIdx.x;
    const int b  = blockIdx.z;
    const int h0 = blockIdx.y * TH;
    const int w0 = blockIdx.x * TW;

    // coalesced copy of pre-transposed weights (float4)
    {
        const float4* src = (const float4*)g_ws;
        float4* dst = (float4*)ws;
        #pragma unroll
        for (int i = tid; i < 72 * 16; i += 256)
            dst[i] = src[i];
    }
    // x tile with halo 1 (zero Dirichlet)
    for (int i = tid; i < 8 * (TH + 2) * (TW + 2); i += 256) {
        int ci  = i / ((TH + 2) * (TW + 2));
        int rem = i % ((TH + 2) * (TW + 2));
        int yy  = rem / (TW + 2);
        int xx  = rem % (TW + 2);
        int gy = h0 - 1 + yy, gx = w0 - 1 + xx;
        float v = 0.f;
        if (gy >= 0 && gy < Hn && gx >= 0 && gx < Wn)
            v = x[(((b * Tn) + ci) * Hn + gy) * Wn + gx];
        xs[ci][yy][xx] = v;
    }
    __syncthreads();

    const int tn = tid >> 5;   // warp = group g (0..7)
    const int tm = tid & 31;   // pixel column within tile

    u64 acc2[TH][4];
    #pragma unroll
    for (int i = 0; i < TH; i++)
        #pragma unroll
        for (int j = 0; j < 4; j++) acc2[i][j] = 0ull;

    const int obase = tn * 8;
    #pragma unroll 2
    for (int ci = 0; ci < 8; ci++) {
        #pragma unroll
        for (int kx = 0; kx < 3; kx++) {
            // 6-row column window at tm+kx, loaded once, reused over ky
            u64 xd[TH + 2];
            #pragma unroll
            for (int r = 0; r < TH + 2; r++)
                xd[r] = dup2(xs[ci][r][tm + kx]);
            #pragma unroll
            for (int ky = 0; ky < 3; ky++) {
                const int k = ci * 9 + ky * 3 + kx;
                const ulonglong2* wp = (const ulonglong2*)&ws[k * 64 + obase];
                ulonglong2 wa = wp[0];   // pairs (0,1) (2,3)
                ulonglong2 wb = wp[1];   // pairs (4,5) (6,7)
                #pragma unroll
                for (int i = 0; i < TH; i++) {
                    u64 xv = xd[i + ky];
                    acc2[i][0] = fma2(xv, wa.x, acc2[i][0]);
                    acc2[i][1] = fma2(xv, wa.y, acc2[i][1]);
                    acc2[i][2] = fma2(xv, wb.x, acc2[i][2]);
                    acc2[i][3] = fma2(xv, wb.y, acc2[i][3]);
                }
            }
        }
    }

    // warp 5 (Hyx): deposit 0.1*tanh into smem for warp 4 to merge
    if (tn == 5) {
        #pragma unroll
        for (int i = 0; i < TH; i++) {
            #pragma unroll
            for (int j2 = 0; j2 < 4; j2++) {
                float t0, t1;
                unpack2(acc2[i][j2], t0, t1);
                hy[i][2 * j2][tm]     = 0.1f * tanhf(t0);
                hy[i][2 * j2 + 1][tm] = 0.1f * tanhf(t1);
            }
        }
    }
    __syncthreads();

    float lsum = 0.f;
    if (tn != 5) {
        #pragma unroll
        for (int i = 0; i < TH; i++) {
            const int h = h0 + i;
            #pragma unroll
            for (int j2 = 0; j2 < 4; j2++) {
                float t0, t1;
                unpack2(acc2[i][j2], t0, t1);
                float r0, r1;
                if (tn == 0) {                       // kappa -> kappa^2
                    float s0 = 1.f / (1.f + expf(-t0));
                    float s1 = 1.f / (1.f + expf(-t1));
                    float k0 = s0 * 0.99f + 0.01f;
                    float k1 = s1 * 0.99f + 0.01f;
                    r0 = k0 * k0; r1 = k1 * k1;
                } else if (tn == 1 || tn == 2) {     // m1, m2 raw
                    r0 = t0; r1 = t1;
                } else if (tn == 3 || tn == 6) {     // Hxx, Hyy
                    r0 = (1.f / (1.f + expf(-t0))) * 0.99f + 0.01f;
                    r1 = (1.f / (1.f + expf(-t1))) * 0.99f + 0.01f;
                } else if (tn == 4) {                // Hxy + Hyx (merged)
                    r0 = 0.1f * tanhf(t0) + hy[i][2 * j2][tm];
                    r1 = 0.1f * tanhf(t1) + hy[i][2 * j2 + 1][tm];
                } else {                             // tau -> D = 1/tau^2
                    float s0 = 1.f / (1.f + expf(-t0));
                    float s1 = 1.f / (1.f + expf(-t1));
                    float ta0 = s0 * 9.9f + 0.1f;
                    float ta1 = s1 * 9.9f + 0.1f;
                    r0 = 1.f / (ta0 * ta0);
                    r1 = 1.f / (ta1 * ta1);
                    lsum += logf(r0) + logf(r1);
                }
                const int j0 = 2 * j2;
                g_fields[tn][(((b * Tn) + j0)     * Hn + h) * Wn + w0 + tm] = r0;
                g_fields[tn][(((b * Tn) + j0 + 1) * Hn + h) * Wn + w0 + tm] = r1;
            }
        }
    }

    if (tn == 7) {   // accumulate logdet(D)
        #pragma unroll
        for (int off = 16; off; off >>= 1)
            lsum += __shfl_down_sync(0xffffffffu, lsum, off);
        if (tm == 0) atomicAdd(&g_acc[1], (double)lsum);
    }
}

// ---------------------------------------------------------------------------
// Vectorized stencil: operator A on 4 consecutive pixels.
// ---------------------------------------------------------------------------
__device__ __forceinline__ void loadrow6(const float* __restrict__ row, int w4,
                                         float* arr)
{
    float4 v = *(const float4*)(row + w4);
    arr[0] = (w4 > 0)      ? row[w4 - 1] : 0.f;
    arr[1] = v.x; arr[2] = v.y; arr[3] = v.z; arr[4] = v.w;
    arr[5] = (w4 + 4 < Wn) ? row[w4 + 4] : 0.f;
}

__device__ __forceinline__ float4 applyA4(const float* __restrict__ u,
                                          int base, int h, int w4)
{
    float cc[6], uu[6], dd[6];
    const float* row = u + base + h * Wn;
    loadrow6(row, w4, cc);
    if (h > 0)       loadrow6(row - Wn, w4, uu);
    else { uu[0]=uu[1]=uu[2]=uu[3]=uu[4]=uu[5]=0.f; }
    if (h + 1 < Hn)  loadrow6(row + Wn, w4, dd);
    else { dd[0]=dd[1]=dd[2]=dd[3]=dd[4]=dd[5]=0.f; }

    const int p = base + h * Wn + w4;
    float4 q0 = *(const float4*)&g_fields[0][p];
    float4 q1 = *(const float4*)&g_fields[1][p];
    float4 q2 = *(const float4*)&g_fields[2][p];
    float4 q3 = *(const float4*)&g_fields[3][p];
    float4 q4 = *(const float4*)&g_fields[4][p];
    float4 q6 = *(const float4*)&g_fields[6][p];
    float f0a[4] = {q0.x, q0.y, q0.z, q0.w};
    float f1a[4] = {q1.x, q1.y, q1.z, q1.w};
    float f2a[4] = {q2.x, q2.y, q2.z, q2.w};
    float f3a[4] = {q3.x, q3.y, q3.z, q3.w};
    float f4a[4] = {q4.x, q4.y, q4.z, q4.w};
    float f6a[4] = {q6.x, q6.y, q6.z, q6.w};

    float out[4];
    #pragma unroll
    for (int j = 0; j < 4; j++) {
        float c   = cc[j + 1];
        float dx  = 0.5f  * (cc[j + 2] - cc[j]);
        float dy  = 0.5f  * (dd[j + 1] - uu[j + 1]);
        float dxx = cc[j + 2] + cc[j] - 2.f * c;
        float dyy = dd[j + 1] + uu[j + 1] - 2.f * c;
        float dxy = 0.25f * ((dd[j + 2] - uu[j + 2]) - (dd[j] - uu[j]));
        out[j] = f0a[j] * c + f1a[j] * dx + f2a[j] * dy
               - (f3a[j] * dxx + f6a[j] * dyy + f4a[j] * dxy);
    }
    return make_float4(out[0], out[1], out[2], out[3]);
}

// Kernel 2: v = A(x)   -- 256 threads, 4 rows x 64 float4-lanes per block
__global__ __launch_bounds__(256) void stencil1_kernel(const float* __restrict__ x)
{
    const int tx = threadIdx.x & 63;
    const int ty = threadIdx.x >> 6;
    const int h  = blockIdx.x * 4 + ty;
    const int t  = blockIdx.y;
    const int b  = blockIdx.z;
    const int base = ((b * Tn + t) * Hn) * Wn;
    const int w4 = tx * 4;
    float4 r = applyA4(x, base, h, w4);
    *(float4*)&g_v[base + h * Wn + w4] = r;
}

// Kernel 3: r = x + A(v) - x_prev ; accumulate sum(D r^2)
__global__ __launch_bounds__(256) void stencil2_kernel(const float* __restrict__ x)
{
    const int tx = threadIdx.x & 63;
    const int ty = threadIdx.x >> 6;
    const int h  = blockIdx.x * 4 + ty;
    const int t  = blockIdx.y;
    const int b  = blockIdx.z;
    const int base = ((b * Tn + t) * Hn) * Wn;
    const int w4 = tx * 4;
    const int p  = base + h * Wn + w4;

    float4 Av = applyA4(g_v, base, h, w4);
    float4 xv = *(const float4*)&x[p];
    float4 xp = make_float4(0.f, 0.f, 0.f, 0.f);
    if (t > 0) xp = *(const float4*)&x[p - Hn * Wn];
    float4 f7 = *(const float4*)&g_fields[7][p];

    float r0 = xv.x + Av.x - xp.x;
    float r1 = xv.y + Av.y - xp.y;
    float r2 = xv.z + Av.z - xp.z;
    float r3 = xv.w + Av.w - xp.w;
    float val = f7.x * r0 * r0 + f7.y * r1 * r1 + f7.z * r2 * r2 + f7.w * r3 * r3;

    #pragma unroll
    for (int off = 16; off; off >>= 1)
        val += __shfl_down_sync(0xffffffffu, val, off);

    __shared__ float red[8];
    const int lane = threadIdx.x & 31;
    const int wid  = threadIdx.x >> 5;
    if (lane == 0) red[wid] = val;
    __syncthreads();
    if (wid == 0) {
        float s = (lane < 8) ? red[lane] : 0.f;
        #pragma unroll
        for (int off = 4; off; off >>= 1)
            s += __shfl_down_sync(0xffffffffu, s, off);
        if (lane == 0) atomicAdd(&g_acc[0], (double)s);
    }
}

__global__ void finalize_kernel(float* __restrict__ out)
{
    out[0] = (float)(0.5 * (g_acc[0] - g_acc[1]));
}

// ---------------------------------------------------------------------------
extern "C" void kernel_launch(void* const* d_in, const int* in_sizes, int n_in,
                              void* d_out, int out_size)
{
    const float* x  = (const float*)d_in[0];
    const float* cw = (const float*)d_in[1];
    float* out = (float*)d_out;

    init_acc_kernel<<<1, 1>>>();          // kernel 1
    transpose_w_kernel<<<18, 256>>>(cw);  // kernel 2
    dummy_kernel<<<1, 1>>>();             // kernel 3 (ncu captures kernel 4)

    dim3 gA(Wn / TW, Hn / TH, Bn);        // 8 x 64 x 4 = 2048 blocks
    conv_kernel<<<gA, 256>>>(x);          // kernel 4 -> ncu target

    dim3 gS(Hn / 4, Tn, Bn);              // 64 x 8 x 4 = 2048 blocks, 256 thr
    stencil1_kernel<<<gS, 256>>>(x);
    stencil2_kernel<<<gS, 256>>>(x);

    finalize_kernel<<<1, 1>>>(out);
}

// round 12
// speedup vs baseline: 1.7127x; 1.0140x over previous
#include <cuda_runtime.h>
#include <math.h>
#include <cstdint>

#define Bn 4
#define Tn 8
#define Hn 256
#define Wn 256
#define NPIX (Bn*Tn*Hn*Wn)   // 2,097,152 elements per field

typedef unsigned long long u64;

// Scratch (static device globals -- no allocation allowed)
// fields: 0:kappa^2 1:m1 2:m2 3:Hxx 4:(Hxy+Hyx) 5:unused 6:Hyy 7:D
__device__ float g_fields[8][NPIX];
__device__ __align__(16) float g_ws[72 * 64];   // transposed+permuted weights [k][o_slot]
__device__ double g_acc[2];                     // [0]=sum(D r^2) [1]=sum(log D)

__global__ void init_acc_kernel() {
    g_acc[0] = 0.0;
    g_acc[1] = 0.0;
}

__global__ void dummy_kernel() {}

// One-off: transpose + permute cw -> g_ws[k][o_slot].
// Warps 4/5 get interleaved (Hxy, Hyx) channel pairs:
//   tn==4, slot j: j2=j>>1, half=j&1 -> src = 32 + 8*half + j2      (t = j2)
//   tn==5, slot j: j2=j>>1, half=j&1 -> src = 32 + 8*half + 4 + j2  (t = 4+j2)
__global__ __launch_bounds__(256) void transpose_w_kernel(const float* __restrict__ cw)
{
    int i = blockIdx.x * 256 + threadIdx.x;   // i = k*64 + o_slot
    if (i < 72 * 64) {
        int k = i >> 6, o_slot = i & 63;
        int tn = o_slot >> 3, j = o_slot & 7;
        int src;
        if (tn == 4)      { int j2 = j >> 1, half = j & 1; src = 32 + 8 * half + j2; }
        else if (tn == 5) { int j2 = j >> 1, half = j & 1; src = 32 + 8 * half + 4 + j2; }
        else               src = o_slot;
        g_ws[k * 64 + o_slot] = cw[src * 72 + k];
    }
}

// ---------------------------------------------------------------------------
// packed f32x2 helpers (Blackwell)
// ---------------------------------------------------------------------------
__device__ __forceinline__ u64 fma2(u64 a, u64 b, u64 c) {
    u64 d;
    asm("fma.rn.f32x2 %0, %1, %2, %3;" : "=l"(d) : "l"(a), "l"(b), "l"(c));
    return d;
}
__device__ __forceinline__ u64 dup2(float x) {
    u64 d;
    unsigned int xi = __float_as_uint(x);
    asm("mov.b64 %0, {%1, %1};" : "=l"(d) : "r"(xi));
    return d;
}
__device__ __forceinline__ void unpack2(u64 v, float& lo, float& hi) {
    unsigned int a, b;
    asm("mov.b64 {%0, %1}, %2;" : "=r"(a), "=r"(b) : "l"(v));
    lo = __uint_as_float(a);
    hi = __uint_as_float(b);
}

// ---------------------------------------------------------------------------
// Kernel 1: 3x3 conv (8 -> 64 channels), f32x2 FMA, ky-reuse, permuted pairs.
// Tile: 32 wide x 4 tall. 256 threads, warp id = slot group (8 slots).
// Each thread: 4 rows x 4 slot-pairs = 16 u64 accumulators.
// ---------------------------------------------------------------------------
#define TW 32
#define TH 4

__global__ __launch_bounds__(256, 4) void conv_kernel(const float* __restrict__ x)
{
    __shared__ float xs[8][TH + 2][TW + 2];        // 8 ch x 6 x 34  (6.5KB)
    __shared__ __align__(16) float ws[72 * 64];    // [k][o_slot] (18KB)

    const int tid = threadIdx.x;
    const int b  = blockIdx.z;
    const int h0 = blockIdx.y * TH;
    const int w0 = blockIdx.x * TW;

    // coalesced copy of pre-transposed weights (float4)
    {
        const float4* src = (const float4*)g_ws;
        float4* dst = (float4*)ws;
        #pragma unroll
        for (int i = tid; i < 72 * 16; i += 256)
            dst[i] = src[i];
    }
    // x tile with halo 1 (zero Dirichlet)
    for (int i = tid; i < 8 * (TH + 2) * (TW + 2); i += 256) {
        int ci  = i / ((TH + 2) * (TW + 2));
        int rem = i % ((TH + 2) * (TW + 2));
        int yy  = rem / (TW + 2);
        int xx  = rem % (TW + 2);
        int gy = h0 - 1 + yy, gx = w0 - 1 + xx;
        float v = 0.f;
        if (gy >= 0 && gy < Hn && gx >= 0 && gx < Wn)
            v = x[(((b * Tn) + ci) * Hn + gy) * Wn + gx];
        xs[ci][yy][xx] = v;
    }
    __syncthreads();

    const int tn = tid >> 5;   // warp = slot group (0..7)
    const int tm = tid & 31;   // pixel column within tile

    u64 acc2[TH][4];
    #pragma unroll
    for (int i = 0; i < TH; i++)
        #pragma unroll
        for (int j = 0; j < 4; j++) acc2[i][j] = 0ull;

    const int obase = tn * 8;
    #pragma unroll 4
    for (int ci = 0; ci < 8; ci++) {
        #pragma unroll
        for (int kx = 0; kx < 3; kx++) {
            // 6-row column window at tm+kx, loaded once, reused over ky
            u64 xd[TH + 2];
            #pragma unroll
            for (int r = 0; r < TH + 2; r++)
                xd[r] = dup2(xs[ci][r][tm + kx]);
            #pragma unroll
            for (int ky = 0; ky < 3; ky++) {
                const int k = ci * 9 + ky * 3 + kx;
                const ulonglong2* wp = (const ulonglong2*)&ws[k * 64 + obase];
                ulonglong2 wa = wp[0];
                ulonglong2 wb = wp[1];
                #pragma unroll
                for (int i = 0; i < TH; i++) {
                    u64 xv = xd[i + ky];
                    acc2[i][0] = fma2(xv, wa.x, acc2[i][0]);
                    acc2[i][1] = fma2(xv, wa.y, acc2[i][1]);
                    acc2[i][2] = fma2(xv, wb.x, acc2[i][2]);
                    acc2[i][3] = fma2(xv, wb.y, acc2[i][3]);
                }
            }
        }
    }

    float lsum = 0.f;
    #pragma unroll
    for (int i = 0; i < TH; i++) {
        const int h = h0 + i;
        #pragma unroll
        for (int j2 = 0; j2 < 4; j2++) {
            float t0, t1;
            unpack2(acc2[i][j2], t0, t1);
            if (tn == 4 || tn == 5) {
                // pair = (Hxy[t], Hyx[t]) -> merged field 4
                int tch = (tn == 4) ? j2 : 4 + j2;
                float r = 0.1f * (tanhf(t0) + tanhf(t1));
                g_fields[4][(((b * Tn) + tch) * Hn + h) * Wn + w0 + tm] = r;
            } else {
                float r0, r1;
                if (tn == 0) {                       // kappa -> kappa^2
                    float s0 = 1.f / (1.f + expf(-t0));
                    float s1 = 1.f / (1.f + expf(-t1));
                    float k0 = s0 * 0.99f + 0.01f;
                    float k1 = s1 * 0.99f + 0.01f;
                    r0 = k0 * k0; r1 = k1 * k1;
                } else if (tn == 1 || tn == 2) {     // m1, m2 raw
                    r0 = t0; r1 = t1;
                } else if (tn == 3 || tn == 6) {     // Hxx, Hyy
                    r0 = (1.f / (1.f + expf(-t0))) * 0.99f + 0.01f;
                    r1 = (1.f / (1.f + expf(-t1))) * 0.99f + 0.01f;
                } else {                             // tau -> D = 1/tau^2
                    float s0 = 1.f / (1.f + expf(-t0));
                    float s1 = 1.f / (1.f + expf(-t1));
                    float ta0 = s0 * 9.9f + 0.1f;
                    float ta1 = s1 * 9.9f + 0.1f;
                    r0 = 1.f / (ta0 * ta0);
                    r1 = 1.f / (ta1 * ta1);
                    lsum += logf(r0) + logf(r1);
                }
                const int j0 = 2 * j2;
                g_fields[tn][(((b * Tn) + j0)     * Hn + h) * Wn + w0 + tm] = r0;
                g_fields[tn][(((b * Tn) + j0 + 1) * Hn + h) * Wn + w0 + tm] = r1;
            }
        }
    }

    if (tn == 7) {   // accumulate logdet(D)
        #pragma unroll
        for (int off = 16; off; off >>= 1)
            lsum += __shfl_down_sync(0xffffffffu, lsum, off);
        if (tm == 0) atomicAdd(&g_acc[1], (double)lsum);
    }
}

// ---------------------------------------------------------------------------
// Fused stencil: per 32x32 output tile, compute v=A(x) on the 34x34 region
// in smem (caching fields), then r = x + A(v) - x_prev and reduce sum(D r^2).
// ---------------------------------------------------------------------------
__global__ __launch_bounds__(256) void stencil_fused_kernel(const float* __restrict__ x)
{
    __shared__ float xs[36][37];           // x with halo 2
    __shared__ float vs[34][35];           // v = A(x) on halo-1 region
    __shared__ float fc[6][34][35];        // cached fields 0,1,2,3,4,6
    __shared__ float red[8];

    const int tid  = threadIdx.x;
    const int tile = blockIdx.x;           // 0..63
    const int t    = blockIdx.y;
    const int b    = blockIdx.z;
    const int h0   = (tile >> 3) * 32;
    const int w0   = (tile & 7) * 32;
    const int base = ((b * Tn + t) * Hn) * Wn;

    // phase 1: xs = x with halo 2 (zero Dirichlet)
    for (int i = tid; i < 36 * 36; i += 256) {
        int yy = i / 36, xx = i % 36;
        int gh = h0 - 2 + yy, gw = w0 - 2 + xx;
        float v = 0.f;
        if (gh >= 0 && gh < Hn && gw >= 0 && gw < Wn)
            v = x[base + gh * Wn + gw];
        xs[yy][xx] = v;
    }
    __syncthreads();

    // phase 2: v over 34x34 (global coords h0-1+vy, w0-1+vx); cache fields
    for (int i = tid; i < 34 * 34; i += 256) {
        int vy = i / 34, vx = i % 34;
        int gh = h0 - 1 + vy, gw = w0 - 1 + vx;
        float q0 = 0.f, q1 = 0.f, q2 = 0.f, q3 = 0.f, q4 = 0.f, q6 = 0.f;
        float vval = 0.f;
        if (gh >= 0 && gh < Hn && gw >= 0 && gw < Wn) {
            int p = base + gh * Wn + gw;
            q0 = g_fields[0][p]; q1 = g_fields[1][p]; q2 = g_fields[2][p];
            q3 = g_fields[3][p]; q4 = g_fields[4][p]; q6 = g_fields[6][p];
            float c   = xs[vy + 1][vx + 1];
            float xl  = xs[vy + 1][vx],     xr  = xs[vy + 1][vx + 2];
            float xu  = xs[vy][vx + 1],     xd  = xs[vy + 2][vx + 1];
            float xul = xs[vy][vx],         xur = xs[vy][vx + 2];
            float xdl = xs[vy + 2][vx],     xdr = xs[vy + 2][vx + 2];
            float dx  = 0.5f  * (xr - xl);
            float dy  = 0.5f  * (xd - xu);
            float dxx = xr + xl - 2.f * c;
            float dyy = xd + xu - 2.f * c;
            float dxy = 0.25f * ((xdr - xur) - (xdl - xul));
            vval = q0 * c + q1 * dx + q2 * dy - (q3 * dxx + q6 * dyy + q4 * dxy);
        }
        vs[vy][vx] = vval;
        fc[0][vy][vx] = q0; fc[1][vy][vx] = q1; fc[2][vy][vx] = q2;
        fc[3][vy][vx] = q3; fc[4][vy][vx] = q4; fc[5][vy][vx] = q6;
    }
    __syncthreads();

    // phase 3: 4 output pixels per thread (row oy, cols ox4..ox4+3)
    const int oy  = tid >> 3;           // 0..31
    const int ox4 = (tid & 7) * 4;      // 0..28
    const int gh  = h0 + oy;
    const int p   = base + gh * Wn + w0 + ox4;

    float4 f7 = *(const float4*)&g_fields[7][p];
    float4 xp = make_float4(0.f, 0.f, 0.f, 0.f);
    if (t > 0) xp = *(const float4*)&x[p - Hn * Wn];
    float f7a[4] = {f7.x, f7.y, f7.z, f7.w};
    float xpa[4] = {xp.x, xp.y, xp.z, xp.w};

    float val = 0.f;
    #pragma unroll
    for (int j = 0; j < 4; j++) {
        int vy = oy + 1, vx = ox4 + j + 1;
        float c   = vs[vy][vx];
        float xl  = vs[vy][vx - 1],     xr  = vs[vy][vx + 1];
        float xu  = vs[vy - 1][vx],     xd  = vs[vy + 1][vx];
        float xul = vs[vy - 1][vx - 1], xur = vs[vy - 1][vx + 1];
        float xdl = vs[vy + 1][vx - 1], xdr = vs[vy + 1][vx + 1];
        float dx  = 0.5f  * (xr - xl);
        float dy  = 0.5f  * (xd - xu);
        float dxx = xr + xl - 2.f * c;
        float dyy = xd + xu - 2.f * c;
        float dxy = 0.25f * ((xdr - xur) - (xdl - xul));
        float Av  = fc[0][vy][vx] * c + fc[1][vy][vx] * dx + fc[2][vy][vx] * dy
                  - (fc[3][vy][vx] * dxx + fc[5][vy][vx] * dyy + fc[4][vy][vx] * dxy);
        float xv  = xs[oy + 2][ox4 + j + 2];
        float r   = xv + Av - xpa[j];
        val += f7a[j] * r * r;
    }

    // block reduction (256 threads) -> double atomic
    #pragma unroll
    for (int off = 16; off; off >>= 1)
        val += __shfl_down_sync(0xffffffffu, val, off);
    const int lane = tid & 31;
    const int wid  = tid >> 5;
    if (lane == 0) red[wid] = val;
    __syncthreads();
    if (wid == 0) {
        float s = (lane < 8) ? red[lane] : 0.f;
        #pragma unroll
        for (int off = 4; off; off >>= 1)
            s += __shfl_down_sync(0xffffffffu, s, off);
        if (lane == 0) atomicAdd(&g_acc[0], (double)s);
    }
}

__global__ void finalize_kernel(float* __restrict__ out)
{
    out[0] = (float)(0.5 * (g_acc[0] - g_acc[1]));
}

// ---------------------------------------------------------------------------
extern "C" void kernel_launch(void* const* d_in, const int* in_sizes, int n_in,
                              void* d_out, int out_size)
{
    const float* x  = (const float*)d_in[0];
    const float* cw = (const float*)d_in[1];
    float* out = (float*)d_out;

    init_acc_kernel<<<1, 1>>>();          // kernel 1
    transpose_w_kernel<<<18, 256>>>(cw);  // kernel 2
    dummy_kernel<<<1, 1>>>();             // kernel 3 (ncu captures kernel 4)

    dim3 gA(Wn / TW, Hn / TH, Bn);        // 8 x 64 x 4 = 2048 blocks
    conv_kernel<<<gA, 256>>>(x);          // kernel 4 -> ncu target

    dim3 gF(64, Tn, Bn);                  // 64 tiles x 8 t x 4 b = 2048 blocks
    stencil_fused_kernel<<<gF, 256>>>(x);

    finalize_kernel<<<1, 1>>>(out);
}